// round 16
// baseline (speedup 1.0000x reference)
#include <cuda_runtime.h>
#include <cuda_fp16.h>
#include <math.h>

#define B    8
#define NPTS 2048
#define BN   (B * NPTS)
#define CMAT ((size_t)B * NPTS * NPTS)

#define CMAX  1.5707964f
#define QSCL  (65535.0f / CMAX)
#define DQ    (1.5707964 / 65535.0)
#define LOG2E 1.4426950408889634
#define LN2   0.6931471805599453

#define RPW   2            // rows per warp -> 16 rows per 256-thread block

// ---------------- scratch (allocation-free: __device__ globals) ----------------
__device__ unsigned short d_C[4][B * NPTS * NPTS];   // Cxx, Cyy, Cxy, Cyx
__device__ float d_pot[2][4][BN];
__device__ float d_fin[4][BN];
__device__ float d_g[2][4][BN];                      // double-buffered weights
__device__ float d_la[BN];                           // log2e * log(alpha)
__device__ float d_lb[BN];

// ---------------- helpers ----------------
__device__ __forceinline__ unsigned int qcost(float t) {
    t = fminf(fmaxf(t, -1.0f + 1e-6f), 1.0f - 1e-6f);
    float ax = fabsf(t);
    float u  = 1.0f - ax;
    float s  = u * __frsqrt_rn(u);
    float p  = -0.0012624911f;
    p = fmaf(p, ax, 0.0066700901f);
    p = fmaf(p, ax, -0.0170881256f);
    p = fmaf(p, ax, 0.0308918810f);
    p = fmaf(p, ax, -0.0501743046f);
    p = fmaf(p, ax, 0.0889789874f);
    p = fmaf(p, ax, -0.2145988016f);
    p = fmaf(p, ax, 1.5707963050f);
    float r = s * p;
    float c = (t < 0.0f) ? (3.14159265359f - r) : r;
    return __float2uint_rn(c * 0.5f * QSCL);
}

// ---------------- kernels ----------------
__global__ void logw_kernel(const float* __restrict__ a, const float* __restrict__ bt,
                            float* __restrict__ la, float* __restrict__ lb) {
    int i = blockIdx.x * blockDim.x + threadIdx.x;
    if (i < BN) {
        float av = a[i];
        la[i] = (float)LOG2E * ((av > 0.f) ? logf(fmaxf(av, 1e-30f)) : -1e5f);
        float bv = bt[i];
        lb[i] = (float)LOG2E * ((bv > 0.f) ? logf(fmaxf(bv, 1e-30f)) : -1e5f);
    }
}

__global__ void cost_all(const float* __restrict__ x, const float* __restrict__ y,
                         unsigned short* __restrict__ Cxx, unsigned short* __restrict__ Cyy,
                         unsigned short* __restrict__ Cxy, unsigned short* __restrict__ Cyx) {
    int job = blockIdx.z >> 3;
    int b   = blockIdx.z & 7;
    const float *P, *Q;
    unsigned short *Co, *Ct;
    int tri;
    if (job == 0)      { P = x; Q = x; Co = Cxx; Ct = Cxx; tri = 1; }
    else if (job == 1) { P = y; Q = y; Co = Cyy; Ct = Cyy; tri = 1; }
    else               { P = x; Q = y; Co = Cxy; Ct = Cyx; tri = 0; }
    if (tri && (int)blockIdx.x < (int)blockIdx.y) return;

    __shared__ float xs[32][3], ys[32][3];
    __shared__ unsigned short t[32][33];
    int n0 = blockIdx.y * 32, m0 = blockIdx.x * 32;
    int tx = threadIdx.x, ty = threadIdx.y;
    int lt = ty * 32 + tx;
    if (lt < 96) {
        xs[lt / 3][lt % 3] = P[((size_t)b * NPTS + n0) * 3 + lt];
        ys[lt / 3][lt % 3] = Q[((size_t)b * NPTS + m0) * 3 + lt];
    }
    __syncthreads();
#pragma unroll
    for (int k = 0; k < 4; k++) {
        int nl = ty + 8 * k;
        float dot = xs[nl][0] * ys[tx][0] + xs[nl][1] * ys[tx][1] + xs[nl][2] * ys[tx][2];
        unsigned int q = qcost(dot);
        t[nl][tx] = (unsigned short)q;
        Co[((size_t)b * NPTS + n0 + nl) * NPTS + m0 + tx] = (unsigned short)q;
    }
    __syncthreads();
#pragma unroll
    for (int k = 0; k < 4; k++) {
        int ml = ty + 8 * k;
        Ct[((size_t)b * NPTS + m0 + ml) * NPTS + n0 + tx] = t[tx][ml];
    }
}

// ---- softmin v9: PRMT unpack; NOMAX = fixed-shift path (eps >= 0.25);
// online-max path gains warp-vote chunk skipping (terms >25 log2 below the
// running max contribute < 2^-25 relative -> droppable vs f16 granularity 2^-11)
// and a single-exp2 merge.
struct SmJobs {
    const unsigned short* C[4];
    const float*          gin[4];
    const float*          potold[4];
    float*                out[4];
    float*                gout[4];
    const float*          lw[4];
};

template <bool NOMAX>
__global__ void __launch_bounds__(256, 5) softmin_fused(
        SmJobs J, float dqs, float goff, float negeln2, float ienl2, int blend) {
    __shared__ float4 sgA[256];      // staged elems 8i..8i+3
    __shared__ float4 sgB[256];      // staged elems 8i+4..8i+7
    __shared__ float  smax[8];

    int tid  = threadIdx.x;
    int warp = tid >> 5, lane = tid & 31;
    int job  = blockIdx.y;
    int rbase = blockIdx.x * (8 * RPW) + warp * RPW;
    int b     = rbase >> 11;

    const unsigned short* Cb = J.C[job];

    const uint4* cp0 = (const uint4*)(Cb + (size_t)rbase * NPTS);
    uint4 q = __ldcs(cp0 + lane);

    // Stage weights. NOMAX: also compute batch max G and fold -G into the stage.
    float G = 0.f;
    {
        const float4* gp4 = (const float4*)(J.gin[job] + b * NPTS);
        float4 gv0 = gp4[tid];
        float4 gv1 = gp4[tid + 256];
        if (NOMAX) {
            float lm = fmaxf(fmaxf(fmaxf(gv0.x, gv0.y), fmaxf(gv0.z, gv0.w)),
                             fmaxf(fmaxf(gv1.x, gv1.y), fmaxf(gv1.z, gv1.w)));
#pragma unroll
            for (int o = 16; o; o >>= 1)
                lm = fmaxf(lm, __shfl_xor_sync(0xffffffffu, lm, o));
            if (lane == 0) smax[warp] = lm;
            __syncthreads();
            G = smax[0];
#pragma unroll
            for (int i = 1; i < 8; i++) G = fmaxf(G, smax[i]);
        }
        float off = goff - G;
        gv0.x += off; gv0.y += off; gv0.z += off; gv0.w += off;
        gv1.x += off; gv1.y += off; gv1.z += off; gv1.w += off;
        if (tid & 1) sgB[tid >> 1] = gv0; else sgA[tid >> 1] = gv0;
        int t2 = tid + 256;
        if (t2 & 1) sgB[t2 >> 1] = gv1; else sgA[t2 >> 1] = gv1;
    }
    __syncthreads();

#pragma unroll
    for (int k = 0; k < RPW; k++) {
        int row = rbase + k;
        float m = 0.f, s = 0.f;
#pragma unroll
        for (int t = 0; t < 8; t++) {
            uint4 qn;
            if (t < 7) {
                qn = __ldcs((const uint4*)(Cb + (size_t)row * NPTS) + (t + 1) * 32 + lane);
            } else if (k < RPW - 1) {
                qn = __ldcs((const uint4*)(Cb + (size_t)(row + 1) * NPTS) + lane);
            }
            int gi = t * 32 + lane;
            float4 gA = sgA[gi];
            float4 gB = sgB[gi];
            float f0 = __uint_as_float(__byte_perm(q.x, 0x4B000000u, 0x7410));
            float f1 = __uint_as_float(__byte_perm(q.x, 0x4B000000u, 0x7432));
            float f2 = __uint_as_float(__byte_perm(q.y, 0x4B000000u, 0x7410));
            float f3 = __uint_as_float(__byte_perm(q.y, 0x4B000000u, 0x7432));
            float f4 = __uint_as_float(__byte_perm(q.z, 0x4B000000u, 0x7410));
            float f5 = __uint_as_float(__byte_perm(q.z, 0x4B000000u, 0x7432));
            float f6 = __uint_as_float(__byte_perm(q.w, 0x4B000000u, 0x7410));
            float f7 = __uint_as_float(__byte_perm(q.w, 0x4B000000u, 0x7432));
            float v0 = fmaf(f0, -dqs, gA.x);
            float v1 = fmaf(f1, -dqs, gA.y);
            float v2 = fmaf(f2, -dqs, gA.z);
            float v3 = fmaf(f3, -dqs, gA.w);
            float v4 = fmaf(f4, -dqs, gB.x);
            float v5 = fmaf(f5, -dqs, gB.y);
            float v6 = fmaf(f6, -dqs, gB.z);
            float v7 = fmaf(f7, -dqs, gB.w);
            if (NOMAX) {
                __half2 h0 = h2exp2(__floats2half2_rn(v0, v1));
                __half2 h1 = h2exp2(__floats2half2_rn(v2, v3));
                h0 = __hadd2(h0, h2exp2(__floats2half2_rn(v4, v5)));
                h1 = __hadd2(h1, h2exp2(__floats2half2_rn(v6, v7)));
                h0 = __hadd2(h0, h1);
                float2 f = __half22float2(h0);
                s += f.x + f.y;
            } else {
                float mc = fmaxf(fmaxf(fmaxf(v0, v1), fmaxf(v2, v3)),
                                 fmaxf(fmaxf(v4, v5), fmaxf(v6, v7)));
                // warp-vote skip: chunk contributes only if some lane's chunk-max
                // is within 25 log2-units of its running max (or first chunk).
                bool need = (t == 0) || (mc >= m - 25.0f);
                if (__ballot_sync(0xffffffffu, need)) {
                    __half2 h0 = h2exp2(__floats2half2_rn(v0 - mc, v1 - mc));
                    __half2 h1 = h2exp2(__floats2half2_rn(v2 - mc, v3 - mc));
                    h0 = __hadd2(h0, h2exp2(__floats2half2_rn(v4 - mc, v5 - mc)));
                    h1 = __hadd2(h1, h2exp2(__floats2half2_rn(v6 - mc, v7 - mc)));
                    h0 = __hadd2(h0, h1);
                    float2 f = __half22float2(h0);
                    float sc = f.x + f.y;
                    if (t == 0) {
                        m = mc; s = sc;
                    } else if (mc > m) {
                        s = fmaf(s, exp2f(m - mc), sc);
                        m = mc;
                    } else {
                        s = fmaf(sc, exp2f(mc - m), s);
                    }
                }
            }
            q = qn;
        }
        if (NOMAX) {
#pragma unroll
            for (int o = 16; o; o >>= 1)
                s += __shfl_xor_sync(0xffffffffu, s, o);
            m = G;
        } else {
#pragma unroll
            for (int o = 16; o; o >>= 1) {
                float mo = __shfl_xor_sync(0xffffffffu, m, o);
                float so = __shfl_xor_sync(0xffffffffu, s, o);
                if (mo > m) {
                    s = fmaf(s, exp2f(m - mo), so);
                    m = mo;
                } else {
                    s = fmaf(so, exp2f(mo - m), s);
                }
            }
        }
        if (lane == 0) {
            float r = negeln2 * (m + log2f(s));
            if (blend) r = 0.5f * (J.potold[job][row] + r);
            J.out[job][row] = r;
            if (J.gout[job])
                J.gout[job][row] = fmaf(r, ienl2, J.lw[job][row]);
        }
    }
}

__global__ void loss_kernel(const float* __restrict__ alpha, const float* __restrict__ beta,
                            float* __restrict__ out) {
    __shared__ double red[8];
    int b = blockIdx.x, tid = threadIdx.x;
    double acc = 0.0;
    for (int i = tid; i < NPTS; i += 256) {
        int idx = b * NPTS + i;
        acc += (double)alpha[idx] * ((double)d_fin[3][idx] - (double)d_fin[0][idx]);
        acc += (double)beta[idx]  * ((double)d_fin[2][idx] - (double)d_fin[1][idx]);
    }
#pragma unroll
    for (int o = 16; o; o >>= 1)
        acc += __shfl_xor_sync(0xffffffffu, acc, o);
    if ((tid & 31) == 0) red[tid >> 5] = acc;
    __syncthreads();
    if (tid == 0) {
        double tot = red[0];
#pragma unroll
        for (int i = 1; i < 8; i++) tot += red[i];
        out[b] = (float)tot;
    }
}

// ---------------- host orchestration ----------------
extern "C" void kernel_launch(void* const* d_in, const int* in_sizes, int n_in,
                              void* d_out, int out_size) {
    const float* alpha = (const float*)d_in[0];
    const float* x     = (const float*)d_in[1];
    const float* beta  = (const float*)d_in[2];
    const float* y     = (const float*)d_in[3];
    float* out = (float*)d_out;

    unsigned short* C_;
    float *pot_, *fin_, *g_, *la_, *lb_;
    cudaGetSymbolAddress((void**)&C_,   d_C);
    cudaGetSymbolAddress((void**)&pot_, d_pot);
    cudaGetSymbolAddress((void**)&fin_, d_fin);
    cudaGetSymbolAddress((void**)&g_,   d_g);
    cudaGetSymbolAddress((void**)&la_,  d_la);
    cudaGetSymbolAddress((void**)&lb_,  d_lb);

    unsigned short* Cxx = C_ + 0 * CMAT;
    unsigned short* Cyy = C_ + 1 * CMAT;
    unsigned short* Cxy = C_ + 2 * CMAT;
    unsigned short* Cyx = C_ + 3 * CMAT;
    auto POT = [&](int buf, int j) { return pot_ + ((size_t)buf * 4 + j) * BN; };
    auto G   = [&](int bank, int j) { return g_ + ((size_t)bank * 4 + j) * BN; };

    logw_kernel<<<(BN + 255) / 256, 256>>>(alpha, beta, la_, lb_);

    cost_all<<<dim3(NPTS / 32, NPTS / 32, 24), dim3(32, 8)>>>(x, y, Cxx, Cyy, Cxy, Cyx);

    const double eps_list[8] = {
        4.0, 3.9999999999999996, 1.0, 0.25, 0.0625, 0.015625, 0.00390625, 0.0025
    };

    const unsigned short* CJ[4] = {Cxx, Cyy, Cyx, Cxy};
    const int GOUTI[4] = {0, 1, 3, 2};
    const float* LW[4] = {la_, lb_, lb_, la_};

    const int gx = BN / (8 * RPW);      // 1024 blocks per job
    dim3 smg(gx, 4);
    const double P23 = 8388608.0;       // 2^23

    // ---- init (eps = 4): fixed-shift path ----
    {
        double eps = 4.0, eps_next = eps_list[0];
        double dqs = DQ * LOG2E / eps;
        SmJobs J;
        for (int j = 0; j < 4; j++) {
            J.C[j] = CJ[j];
            J.gin[j] = (j == 0 || j == 2) ? la_ : lb_;
            J.potold[j] = nullptr;
            J.out[j] = POT(0, j);
            J.gout[j] = G(0, GOUTI[j]);
            J.lw[j] = LW[j];
        }
        softmin_fused<true><<<smg, 256>>>(J, (float)dqs, (float)(P23 * dqs),
                                          (float)(-eps * LN2),
                                          (float)(LOG2E / eps_next), 0);
    }

    // ---- annealed loop: fixed-shift for eps >= 0.25 (i < 4), online-max after ----
    int cur = 0, gb = 0;
    for (int i = 0; i < 8; i++) {
        double eps = eps_list[i];
        double eps_next = (i < 7) ? eps_list[i + 1] : 0.0025;
        double dqs = DQ * LOG2E / eps;
        int nxt = cur ^ 1;
        SmJobs J;
        for (int j = 0; j < 4; j++) {
            J.C[j] = CJ[j];
            J.gin[j] = G(gb, j);
            J.potold[j] = POT(cur, j);
            J.out[j] = POT(nxt, j);
            J.gout[j] = G(gb ^ 1, GOUTI[j]);
            J.lw[j] = LW[j];
        }
        if (i < 4)
            softmin_fused<true><<<smg, 256>>>(J, (float)dqs, (float)(P23 * dqs),
                                              (float)(-eps * LN2),
                                              (float)(LOG2E / eps_next), 1);
        else
            softmin_fused<false><<<smg, 256>>>(J, (float)dqs, (float)(P23 * dqs),
                                               (float)(-eps * LN2),
                                               (float)(LOG2E / eps_next), 1);
        cur = nxt;
        gb ^= 1;
    }

    // ---- final extrapolation (eps = 0.0025), online-max + skip;
    //      SEQUENTIAL: b_x uses fresh a_y ----
    {
        double eps = 0.0025;
        double dqs = DQ * LOG2E / eps;
        float nel = (float)(-eps * LN2);
        float ien = (float)(LOG2E / eps);
        SmJobs J;
        for (int j = 0; j < 3; j++) {
            J.C[j] = CJ[j];
            J.gin[j] = G(gb, j);
            J.potold[j] = nullptr;
            J.out[j] = fin_ + (size_t)j * BN;
            J.gout[j] = (j == 2) ? G(gb ^ 1, 3) : nullptr;
            J.lw[j] = LW[j];
        }
        J.C[3] = CJ[3]; J.gin[3] = G(gb, 3); J.potold[3] = nullptr;
        J.out[3] = fin_ + 3 * (size_t)BN; J.gout[3] = nullptr; J.lw[3] = LW[3];
        softmin_fused<false><<<dim3(gx, 3), 256>>>(J, (float)dqs, (float)(P23 * dqs),
                                                   nel, ien, 0);

        SmJobs J2;
        for (int j = 0; j < 4; j++) {
            J2.C[j] = Cxy; J2.gin[j] = G(gb ^ 1, 3); J2.potold[j] = nullptr;
            J2.out[j] = fin_ + 3 * (size_t)BN; J2.gout[j] = nullptr; J2.lw[j] = lb_;
        }
        softmin_fused<false><<<dim3(gx, 1), 256>>>(J2, (float)dqs, (float)(P23 * dqs),
                                                   nel, ien, 0);
    }

    loss_kernel<<<B, 256>>>(alpha, beta, out);
}

// round 17
// speedup vs baseline: 1.2929x; 1.2929x over previous
#include <cuda_runtime.h>
#include <cuda_fp16.h>
#include <math.h>

#define B    8
#define NPTS 2048
#define BN   (B * NPTS)
#define CMAT ((size_t)B * NPTS * NPTS)

#define CMAX  1.5707964f
#define QSCL  (65535.0f / CMAX)
#define DQ    (1.5707964 / 65535.0)
#define LOG2E 1.4426950408889634
#define LN2   0.6931471805599453

#define RPW   2            // rows per warp -> 16 rows per 256-thread block

// ---------------- scratch (allocation-free: __device__ globals) ----------------
__device__ unsigned short d_C[4][B * NPTS * NPTS];   // Cxx, Cyy, Cxy, Cyx
__device__ float d_pot[2][4][BN];
__device__ float d_fin[4][BN];
__device__ float d_g[2][4][BN];                      // double-buffered weights
__device__ float d_la[BN];                           // log2e * log(alpha)
__device__ float d_lb[BN];

// ---------------- helpers ----------------
__device__ __forceinline__ unsigned int qcost(float t) {
    t = fminf(fmaxf(t, -1.0f + 1e-6f), 1.0f - 1e-6f);
    float ax = fabsf(t);
    float u  = 1.0f - ax;
    float s  = u * __frsqrt_rn(u);
    float p  = -0.0012624911f;
    p = fmaf(p, ax, 0.0066700901f);
    p = fmaf(p, ax, -0.0170881256f);
    p = fmaf(p, ax, 0.0308918810f);
    p = fmaf(p, ax, -0.0501743046f);
    p = fmaf(p, ax, 0.0889789874f);
    p = fmaf(p, ax, -0.2145988016f);
    p = fmaf(p, ax, 1.5707963050f);
    float r = s * p;
    float c = (t < 0.0f) ? (3.14159265359f - r) : r;
    return __float2uint_rn(c * 0.5f * QSCL);
}

// branchless single-MUFU (m,s) merge: algebraically s*2^(m-M)+sc*2^(mc-M)
__device__ __forceinline__ void msmerge(float& m, float& s, float mc, float sc) {
    float d  = mc - m;
    float e  = exp2f(-fabsf(d));
    float sa = fmaf(s, e, sc);    // case mc > m
    float sb = fmaf(sc, e, s);    // case mc <= m
    s = (d > 0.f) ? sa : sb;
    m = fmaxf(m, mc);
}

// ---------------- kernels ----------------
__global__ void logw_kernel(const float* __restrict__ a, const float* __restrict__ bt,
                            float* __restrict__ la, float* __restrict__ lb) {
    int i = blockIdx.x * blockDim.x + threadIdx.x;
    if (i < BN) {
        float av = a[i];
        la[i] = (float)LOG2E * ((av > 0.f) ? logf(fmaxf(av, 1e-30f)) : -1e5f);
        float bv = bt[i];
        lb[i] = (float)LOG2E * ((bv > 0.f) ? logf(fmaxf(bv, 1e-30f)) : -1e5f);
    }
}

__global__ void cost_all(const float* __restrict__ x, const float* __restrict__ y,
                         unsigned short* __restrict__ Cxx, unsigned short* __restrict__ Cyy,
                         unsigned short* __restrict__ Cxy, unsigned short* __restrict__ Cyx) {
    int job = blockIdx.z >> 3;
    int b   = blockIdx.z & 7;
    const float *P, *Q;
    unsigned short *Co, *Ct;
    int tri;
    if (job == 0)      { P = x; Q = x; Co = Cxx; Ct = Cxx; tri = 1; }
    else if (job == 1) { P = y; Q = y; Co = Cyy; Ct = Cyy; tri = 1; }
    else               { P = x; Q = y; Co = Cxy; Ct = Cyx; tri = 0; }
    if (tri && (int)blockIdx.x < (int)blockIdx.y) return;

    __shared__ float xs[32][3], ys[32][3];
    __shared__ unsigned short t[32][33];
    int n0 = blockIdx.y * 32, m0 = blockIdx.x * 32;
    int tx = threadIdx.x, ty = threadIdx.y;
    int lt = ty * 32 + tx;
    if (lt < 96) {
        xs[lt / 3][lt % 3] = P[((size_t)b * NPTS + n0) * 3 + lt];
        ys[lt / 3][lt % 3] = Q[((size_t)b * NPTS + m0) * 3 + lt];
    }
    __syncthreads();
#pragma unroll
    for (int k = 0; k < 4; k++) {
        int nl = ty + 8 * k;
        float dot = xs[nl][0] * ys[tx][0] + xs[nl][1] * ys[tx][1] + xs[nl][2] * ys[tx][2];
        unsigned int q = qcost(dot);
        t[nl][tx] = (unsigned short)q;
        Co[((size_t)b * NPTS + n0 + nl) * NPTS + m0 + tx] = (unsigned short)q;
    }
    __syncthreads();
#pragma unroll
    for (int k = 0; k < 4; k++) {
        int ml = ty + 8 * k;
        Ct[((size_t)b * NPTS + m0 + ml) * NPTS + n0 + tx] = t[tx][ml];
    }
}

// ---- softmin v10 = R15 with branchless single-MUFU merges.
struct SmJobs {
    const unsigned short* C[4];
    const float*          gin[4];
    const float*          potold[4];
    float*                out[4];
    float*                gout[4];
    const float*          lw[4];
};

template <bool NOMAX>
__global__ void __launch_bounds__(256, 5) softmin_fused(
        SmJobs J, float dqs, float goff, float negeln2, float ienl2, int blend) {
    __shared__ float4 sgA[256];      // staged elems 8i..8i+3
    __shared__ float4 sgB[256];      // staged elems 8i+4..8i+7
    __shared__ float  smax[8];

    int tid  = threadIdx.x;
    int warp = tid >> 5, lane = tid & 31;
    int job  = blockIdx.y;
    int rbase = blockIdx.x * (8 * RPW) + warp * RPW;
    int b     = rbase >> 11;

    const unsigned short* Cb = J.C[job];

    const uint4* cp0 = (const uint4*)(Cb + (size_t)rbase * NPTS);
    uint4 q = __ldcs(cp0 + lane);

    // Stage weights. NOMAX: also compute batch max G and fold -G into the stage.
    float G = 0.f;
    {
        const float4* gp4 = (const float4*)(J.gin[job] + b * NPTS);
        float4 gv0 = gp4[tid];
        float4 gv1 = gp4[tid + 256];
        if (NOMAX) {
            float lm = fmaxf(fmaxf(fmaxf(gv0.x, gv0.y), fmaxf(gv0.z, gv0.w)),
                             fmaxf(fmaxf(gv1.x, gv1.y), fmaxf(gv1.z, gv1.w)));
#pragma unroll
            for (int o = 16; o; o >>= 1)
                lm = fmaxf(lm, __shfl_xor_sync(0xffffffffu, lm, o));
            if (lane == 0) smax[warp] = lm;
            __syncthreads();
            G = smax[0];
#pragma unroll
            for (int i = 1; i < 8; i++) G = fmaxf(G, smax[i]);
        }
        float off = goff - G;
        gv0.x += off; gv0.y += off; gv0.z += off; gv0.w += off;
        gv1.x += off; gv1.y += off; gv1.z += off; gv1.w += off;
        if (tid & 1) sgB[tid >> 1] = gv0; else sgA[tid >> 1] = gv0;
        int t2 = tid + 256;
        if (t2 & 1) sgB[t2 >> 1] = gv1; else sgA[t2 >> 1] = gv1;
    }
    __syncthreads();

#pragma unroll
    for (int k = 0; k < RPW; k++) {
        int row = rbase + k;
        float m = 0.f, s = 0.f;
#pragma unroll
        for (int t = 0; t < 8; t++) {
            uint4 qn;
            if (t < 7) {
                qn = __ldcs((const uint4*)(Cb + (size_t)row * NPTS) + (t + 1) * 32 + lane);
            } else if (k < RPW - 1) {
                qn = __ldcs((const uint4*)(Cb + (size_t)(row + 1) * NPTS) + lane);
            }
            int gi = t * 32 + lane;
            float4 gA = sgA[gi];
            float4 gB = sgB[gi];
            float f0 = __uint_as_float(__byte_perm(q.x, 0x4B000000u, 0x7410));
            float f1 = __uint_as_float(__byte_perm(q.x, 0x4B000000u, 0x7432));
            float f2 = __uint_as_float(__byte_perm(q.y, 0x4B000000u, 0x7410));
            float f3 = __uint_as_float(__byte_perm(q.y, 0x4B000000u, 0x7432));
            float f4 = __uint_as_float(__byte_perm(q.z, 0x4B000000u, 0x7410));
            float f5 = __uint_as_float(__byte_perm(q.z, 0x4B000000u, 0x7432));
            float f6 = __uint_as_float(__byte_perm(q.w, 0x4B000000u, 0x7410));
            float f7 = __uint_as_float(__byte_perm(q.w, 0x4B000000u, 0x7432));
            float v0 = fmaf(f0, -dqs, gA.x);
            float v1 = fmaf(f1, -dqs, gA.y);
            float v2 = fmaf(f2, -dqs, gA.z);
            float v3 = fmaf(f3, -dqs, gA.w);
            float v4 = fmaf(f4, -dqs, gB.x);
            float v5 = fmaf(f5, -dqs, gB.y);
            float v6 = fmaf(f6, -dqs, gB.z);
            float v7 = fmaf(f7, -dqs, gB.w);
            if (NOMAX) {
                __half2 h0 = h2exp2(__floats2half2_rn(v0, v1));
                __half2 h1 = h2exp2(__floats2half2_rn(v2, v3));
                h0 = __hadd2(h0, h2exp2(__floats2half2_rn(v4, v5)));
                h1 = __hadd2(h1, h2exp2(__floats2half2_rn(v6, v7)));
                h0 = __hadd2(h0, h1);
                float2 f = __half22float2(h0);
                s += f.x + f.y;
            } else {
                float mc = fmaxf(fmaxf(fmaxf(v0, v1), fmaxf(v2, v3)),
                                 fmaxf(fmaxf(v4, v5), fmaxf(v6, v7)));
                __half2 h0 = h2exp2(__floats2half2_rn(v0 - mc, v1 - mc));
                __half2 h1 = h2exp2(__floats2half2_rn(v2 - mc, v3 - mc));
                h0 = __hadd2(h0, h2exp2(__floats2half2_rn(v4 - mc, v5 - mc)));
                h1 = __hadd2(h1, h2exp2(__floats2half2_rn(v6 - mc, v7 - mc)));
                h0 = __hadd2(h0, h1);
                float2 f = __half22float2(h0);
                float sc = f.x + f.y;
                if (t == 0) {
                    m = mc; s = sc;
                } else {
                    msmerge(m, s, mc, sc);
                }
            }
            q = qn;
        }
        if (NOMAX) {
#pragma unroll
            for (int o = 16; o; o >>= 1)
                s += __shfl_xor_sync(0xffffffffu, s, o);
            m = G;
        } else {
#pragma unroll
            for (int o = 16; o; o >>= 1) {
                float mo = __shfl_xor_sync(0xffffffffu, m, o);
                float so = __shfl_xor_sync(0xffffffffu, s, o);
                msmerge(m, s, mo, so);
            }
        }
        if (lane == 0) {
            float r = negeln2 * (m + log2f(s));
            if (blend) r = 0.5f * (J.potold[job][row] + r);
            J.out[job][row] = r;
            if (J.gout[job])
                J.gout[job][row] = fmaf(r, ienl2, J.lw[job][row]);
        }
    }
}

__global__ void loss_kernel(const float* __restrict__ alpha, const float* __restrict__ beta,
                            float* __restrict__ out) {
    __shared__ double red[8];
    int b = blockIdx.x, tid = threadIdx.x;
    double acc = 0.0;
    for (int i = tid; i < NPTS; i += 256) {
        int idx = b * NPTS + i;
        acc += (double)alpha[idx] * ((double)d_fin[3][idx] - (double)d_fin[0][idx]);
        acc += (double)beta[idx]  * ((double)d_fin[2][idx] - (double)d_fin[1][idx]);
    }
#pragma unroll
    for (int o = 16; o; o >>= 1)
        acc += __shfl_xor_sync(0xffffffffu, acc, o);
    if ((tid & 31) == 0) red[tid >> 5] = acc;
    __syncthreads();
    if (tid == 0) {
        double tot = red[0];
#pragma unroll
        for (int i = 1; i < 8; i++) tot += red[i];
        out[b] = (float)tot;
    }
}

// ---------------- host orchestration ----------------
extern "C" void kernel_launch(void* const* d_in, const int* in_sizes, int n_in,
                              void* d_out, int out_size) {
    const float* alpha = (const float*)d_in[0];
    const float* x     = (const float*)d_in[1];
    const float* beta  = (const float*)d_in[2];
    const float* y     = (const float*)d_in[3];
    float* out = (float*)d_out;

    unsigned short* C_;
    float *pot_, *fin_, *g_, *la_, *lb_;
    cudaGetSymbolAddress((void**)&C_,   d_C);
    cudaGetSymbolAddress((void**)&pot_, d_pot);
    cudaGetSymbolAddress((void**)&fin_, d_fin);
    cudaGetSymbolAddress((void**)&g_,   d_g);
    cudaGetSymbolAddress((void**)&la_,  d_la);
    cudaGetSymbolAddress((void**)&lb_,  d_lb);

    unsigned short* Cxx = C_ + 0 * CMAT;
    unsigned short* Cyy = C_ + 1 * CMAT;
    unsigned short* Cxy = C_ + 2 * CMAT;
    unsigned short* Cyx = C_ + 3 * CMAT;
    auto POT = [&](int buf, int j) { return pot_ + ((size_t)buf * 4 + j) * BN; };
    auto G   = [&](int bank, int j) { return g_ + ((size_t)bank * 4 + j) * BN; };

    logw_kernel<<<(BN + 255) / 256, 256>>>(alpha, beta, la_, lb_);

    cost_all<<<dim3(NPTS / 32, NPTS / 32, 24), dim3(32, 8)>>>(x, y, Cxx, Cyy, Cxy, Cyx);

    const double eps_list[8] = {
        4.0, 3.9999999999999996, 1.0, 0.25, 0.0625, 0.015625, 0.00390625, 0.0025
    };

    const unsigned short* CJ[4] = {Cxx, Cyy, Cyx, Cxy};
    const int GOUTI[4] = {0, 1, 3, 2};
    const float* LW[4] = {la_, lb_, lb_, la_};

    const int gx = BN / (8 * RPW);      // 1024 blocks per job
    dim3 smg(gx, 4);
    const double P23 = 8388608.0;       // 2^23

    // ---- init (eps = 4): fixed-shift path ----
    {
        double eps = 4.0, eps_next = eps_list[0];
        double dqs = DQ * LOG2E / eps;
        SmJobs J;
        for (int j = 0; j < 4; j++) {
            J.C[j] = CJ[j];
            J.gin[j] = (j == 0 || j == 2) ? la_ : lb_;
            J.potold[j] = nullptr;
            J.out[j] = POT(0, j);
            J.gout[j] = G(0, GOUTI[j]);
            J.lw[j] = LW[j];
        }
        softmin_fused<true><<<smg, 256>>>(J, (float)dqs, (float)(P23 * dqs),
                                          (float)(-eps * LN2),
                                          (float)(LOG2E / eps_next), 0);
    }

    // ---- annealed loop: fixed-shift for eps >= 0.25 (i < 4), online-max after ----
    int cur = 0, gb = 0;
    for (int i = 0; i < 8; i++) {
        double eps = eps_list[i];
        double eps_next = (i < 7) ? eps_list[i + 1] : 0.0025;
        double dqs = DQ * LOG2E / eps;
        int nxt = cur ^ 1;
        SmJobs J;
        for (int j = 0; j < 4; j++) {
            J.C[j] = CJ[j];
            J.gin[j] = G(gb, j);
            J.potold[j] = POT(cur, j);
            J.out[j] = POT(nxt, j);
            J.gout[j] = G(gb ^ 1, GOUTI[j]);
            J.lw[j] = LW[j];
        }
        if (i < 4)
            softmin_fused<true><<<smg, 256>>>(J, (float)dqs, (float)(P23 * dqs),
                                              (float)(-eps * LN2),
                                              (float)(LOG2E / eps_next), 1);
        else
            softmin_fused<false><<<smg, 256>>>(J, (float)dqs, (float)(P23 * dqs),
                                               (float)(-eps * LN2),
                                               (float)(LOG2E / eps_next), 1);
        cur = nxt;
        gb ^= 1;
    }

    // ---- final extrapolation (eps = 0.0025), online-max;
    //      SEQUENTIAL: b_x uses fresh a_y ----
    {
        double eps = 0.0025;
        double dqs = DQ * LOG2E / eps;
        float nel = (float)(-eps * LN2);
        float ien = (float)(LOG2E / eps);
        SmJobs J;
        for (int j = 0; j < 3; j++) {
            J.C[j] = CJ[j];
            J.gin[j] = G(gb, j);
            J.potold[j] = nullptr;
            J.out[j] = fin_ + (size_t)j * BN;
            J.gout[j] = (j == 2) ? G(gb ^ 1, 3) : nullptr;
            J.lw[j] = LW[j];
        }
        J.C[3] = CJ[3]; J.gin[3] = G(gb, 3); J.potold[3] = nullptr;
        J.out[3] = fin_ + 3 * (size_t)BN; J.gout[3] = nullptr; J.lw[3] = LW[3];
        softmin_fused<false><<<dim3(gx, 3), 256>>>(J, (float)dqs, (float)(P23 * dqs),
                                                   nel, ien, 0);

        SmJobs J2;
        for (int j = 0; j < 4; j++) {
            J2.C[j] = Cxy; J2.gin[j] = G(gb ^ 1, 3); J2.potold[j] = nullptr;
            J2.out[j] = fin_ + 3 * (size_t)BN; J2.gout[j] = nullptr; J2.lw[j] = lb_;
        }
        softmin_fused<false><<<dim3(gx, 1), 256>>>(J2, (float)dqs, (float)(P23 * dqs),
                                                   nel, ien, 0);
    }

    loss_kernel<<<B, 256>>>(alpha, beta, out);
}